// round 1
// baseline (speedup 1.0000x reference)
#include <cuda_runtime.h>

#define Bdim 16
#define Tdim 1024
#define Cdim 1024
#define T2 (Tdim + 2)
#define EPS 1e-5f

// Scratch for layer-normed BOS/EOS embeddings (allocation-free __device__ globals)
__device__ float g_bos_ln[Cdim];
__device__ float g_eos_ln[Cdim];

__device__ __forceinline__ float block_sum_256(float v, float* sm) {
    int lane = threadIdx.x & 31;
    int w    = threadIdx.x >> 5;
    #pragma unroll
    for (int o = 16; o > 0; o >>= 1) v += __shfl_xor_sync(0xffffffffu, v, o);
    if (lane == 0) sm[w] = v;
    __syncthreads();
    if (w == 0) {
        float t = (lane < 8) ? sm[lane] : 0.0f;
        #pragma unroll
        for (int o = 4; o > 0; o >>= 1) t += __shfl_xor_sync(0xffffffffu, t, o);
        if (lane == 0) sm[0] = t;
    }
    __syncthreads();
    float r = sm[0];
    __syncthreads();   // protect sm for next reuse
    return r;
}

// Block 0 -> bos, block 1 -> eos. 256 threads, 4 floats/thread.
__global__ void special_ln_kernel(const float* __restrict__ bos,
                                  const float* __restrict__ eos,
                                  const float* __restrict__ gamma,
                                  const float* __restrict__ beta) {
    const float* src = (blockIdx.x == 0) ? bos : eos;
    float*       dst = (blockIdx.x == 0) ? g_bos_ln : g_eos_ln;
    __shared__ float sm[8];
    int tid = threadIdx.x;
    float4 v = reinterpret_cast<const float4*>(src)[tid];
    float mu = block_sum_256(v.x + v.y + v.z + v.w, sm) * (1.0f / Cdim);
    float dx = v.x - mu, dy = v.y - mu, dz = v.z - mu, dw = v.w - mu;
    float var = block_sum_256(dx*dx + dy*dy + dz*dz + dw*dw, sm) * (1.0f / Cdim);
    float inv = rsqrtf(var + EPS);
    float4 g  = reinterpret_cast<const float4*>(gamma)[tid];
    float4 bt = reinterpret_cast<const float4*>(beta)[tid];
    float4 o;
    o.x = dx * inv * g.x + bt.x;
    o.y = dy * inv * g.y + bt.y;
    o.z = dz * inv * g.z + bt.z;
    o.w = dw * inv * g.w + bt.w;
    reinterpret_cast<float4*>(dst)[tid] = o;
}

// One CTA per output row (b, t2). 256 threads x float4 = 1024 channels.
__global__ void __launch_bounds__(256)
embed_kernel(const float* __restrict__ x,
             const int*   __restrict__ lengths,
             const float* __restrict__ pos_table,
             const float* __restrict__ scale_p,
             const float* __restrict__ gamma,
             const float* __restrict__ beta,
             float* __restrict__ out,
             long long out_size) {
    const int row = blockIdx.x;          // 0 .. B*T2-1
    const int b   = row / T2;
    const int t2  = row % T2;
    const int l   = lengths[b];
    const int tid = threadIdx.x;

    // Select source row
    float4 v;
    if (t2 == 0) {
        v = reinterpret_cast<const float4*>(g_bos_ln)[tid];
    } else if (t2 == l + 1) {
        v = reinterpret_cast<const float4*>(g_eos_ln)[tid];
    } else if (t2 >= 1 && t2 <= l) {
        const float* xr = x + ((size_t)(b * Tdim + (t2 - 1))) * Cdim;
        v = reinterpret_cast<const float4*>(xr)[tid];
    } else {
        v = make_float4(0.f, 0.f, 0.f, 0.f);
    }

    // positions: nonpad (t2 < l+2) -> t2+2 ; pad -> PAD_IDX (=1)
    const int pos = (t2 < l + 2) ? (t2 + 2) : 1;
    const float4 pe = reinterpret_cast<const float4*>(pos_table + (size_t)pos * Cdim)[tid];

    const float sc = scale_p[0];
    v.x = v.x * sc + pe.x;
    v.y = v.y * sc + pe.y;
    v.z = v.z * sc + pe.z;
    v.w = v.w * sc + pe.w;

    // LayerNorm over C
    __shared__ float sm[8];
    const float mu = block_sum_256(v.x + v.y + v.z + v.w, sm) * (1.0f / Cdim);
    const float dx = v.x - mu, dy = v.y - mu, dz = v.z - mu, dw = v.w - mu;
    const float var = block_sum_256(dx*dx + dy*dy + dz*dz + dw*dw, sm) * (1.0f / Cdim);
    const float inv = rsqrtf(var + EPS);

    const float4 g  = reinterpret_cast<const float4*>(gamma)[tid];
    const float4 bt = reinterpret_cast<const float4*>(beta)[tid];
    float4 o;
    o.x = dx * inv * g.x + bt.x;
    o.y = dy * inv * g.y + bt.y;
    o.z = dz * inv * g.z + bt.z;
    o.w = dw * inv * g.w + bt.w;
    reinterpret_cast<float4*>(out + (size_t)row * Cdim)[tid] = o;

    // Auxiliary outputs (pad2 mask, l2) appended after the main tensor if present
    const long long XSZ = (long long)Bdim * T2 * Cdim;
    if (out_size >= XSZ + (long long)Bdim * T2) {
        if (tid == 0) out[XSZ + row] = (t2 >= l + 2) ? 1.0f : 0.0f;
        if (tid == 1 && t2 == 0 && out_size >= XSZ + (long long)Bdim * T2 + Bdim)
            out[XSZ + (long long)Bdim * T2 + b] = (float)(l + 2);
    }
}

extern "C" void kernel_launch(void* const* d_in, const int* in_sizes, int n_in,
                              void* d_out, int out_size) {
    const float* x         = (const float*)d_in[0];
    const int*   lengths   = (const int*)  d_in[1];
    const float* bos_emb   = (const float*)d_in[2];
    const float* eos_emb   = (const float*)d_in[3];
    const float* ln_s_g    = (const float*)d_in[4];
    const float* ln_s_b    = (const float*)d_in[5];
    const float* pos_table = (const float*)d_in[6];
    const float* scale     = (const float*)d_in[7];
    const float* ln_e_g    = (const float*)d_in[8];
    const float* ln_e_b    = (const float*)d_in[9];
    float* out = (float*)d_out;

    special_ln_kernel<<<2, 256>>>(bos_emb, eos_emb, ln_s_g, ln_s_b);
    embed_kernel<<<Bdim * T2, 256>>>(x, lengths, pos_table, scale,
                                     ln_e_g, ln_e_b, out, (long long)out_size);
}

// round 2
// speedup vs baseline: 1.4437x; 1.4437x over previous
#include <cuda_runtime.h>

#define Bdim 16
#define Tdim 1024
#define Cdim 1024
#define T2 (Tdim + 2)
#define NROWS (Bdim * T2)
#define EPS 1e-5f
#define WARPS_PER_CTA 8

// Fused warp-per-row speech embedder.
// Each warp owns one output row (b, t2): 1024 channels = 8 x float4 per lane.
// No __syncthreads anywhere; reductions are warp shuffles only.
__global__ void __launch_bounds__(256)
embed_kernel(const float* __restrict__ x,
             const int*   __restrict__ lengths,
             const float* __restrict__ bos_emb,
             const float* __restrict__ eos_emb,
             const float* __restrict__ ln_s_g,
             const float* __restrict__ ln_s_b,
             const float* __restrict__ pos_table,
             const float* __restrict__ scale_p,
             const float* __restrict__ ln_e_g,
             const float* __restrict__ ln_e_b,
             float* __restrict__ out,
             long long out_size) {
    const int gwarp = (blockIdx.x * WARPS_PER_CTA) + (threadIdx.x >> 5);
    if (gwarp >= NROWS) return;
    const int lane = threadIdx.x & 31;
    const int b  = gwarp / T2;
    const int t2 = gwarp % T2;
    const int l  = lengths[b];
    const float sc = scale_p[0];

    float4 v[8];

    if (t2 == 0 || t2 == l + 1) {
        // Inline layernorm of the special embedding (only ~32 warps hit this)
        const float4* src = reinterpret_cast<const float4*>((t2 == 0) ? bos_emb : eos_emb);
        float s = 0.f, s2 = 0.f;
        #pragma unroll
        for (int c = 0; c < 8; c++) {
            v[c] = src[lane + 32 * c];
            s  += v[c].x + v[c].y + v[c].z + v[c].w;
            s2 += v[c].x*v[c].x + v[c].y*v[c].y + v[c].z*v[c].z + v[c].w*v[c].w;
        }
        #pragma unroll
        for (int o = 16; o > 0; o >>= 1) {
            s  += __shfl_xor_sync(0xffffffffu, s,  o);
            s2 += __shfl_xor_sync(0xffffffffu, s2, o);
        }
        const float mu  = s * (1.0f / Cdim);
        const float var = s2 * (1.0f / Cdim) - mu * mu;
        const float inv = rsqrtf(var + EPS);
        const float4* gg = reinterpret_cast<const float4*>(ln_s_g);
        const float4* bb = reinterpret_cast<const float4*>(ln_s_b);
        #pragma unroll
        for (int c = 0; c < 8; c++) {
            const float4 g = gg[lane + 32 * c];
            const float4 bt = bb[lane + 32 * c];
            v[c].x = (v[c].x - mu) * inv * g.x + bt.x;
            v[c].y = (v[c].y - mu) * inv * g.y + bt.y;
            v[c].z = (v[c].z - mu) * inv * g.z + bt.z;
            v[c].w = (v[c].w - mu) * inv * g.w + bt.w;
        }
    } else if (t2 >= 1 && t2 <= l) {
        const float4* xr = reinterpret_cast<const float4*>(
            x + ((size_t)(b * Tdim + (t2 - 1))) * Cdim);
        #pragma unroll
        for (int c = 0; c < 8; c++) v[c] = xr[lane + 32 * c];
    } else {
        #pragma unroll
        for (int c = 0; c < 8; c++) v[c] = make_float4(0.f, 0.f, 0.f, 0.f);
    }

    // Positional embedding: nonpad -> row t2+2, pad -> PAD_IDX row (1)
    const int pos = (t2 < l + 2) ? (t2 + 2) : 1;
    const float4* per = reinterpret_cast<const float4*>(pos_table + (size_t)pos * Cdim);

    float s = 0.f, s2 = 0.f;
    #pragma unroll
    for (int c = 0; c < 8; c++) {
        const float4 p = per[lane + 32 * c];
        v[c].x = v[c].x * sc + p.x;
        v[c].y = v[c].y * sc + p.y;
        v[c].z = v[c].z * sc + p.z;
        v[c].w = v[c].w * sc + p.w;
        s  += v[c].x + v[c].y + v[c].z + v[c].w;
        s2 += v[c].x*v[c].x + v[c].y*v[c].y + v[c].z*v[c].z + v[c].w*v[c].w;
    }
    #pragma unroll
    for (int o = 16; o > 0; o >>= 1) {
        s  += __shfl_xor_sync(0xffffffffu, s,  o);
        s2 += __shfl_xor_sync(0xffffffffu, s2, o);
    }
    const float mu  = s * (1.0f / Cdim);
    const float var = s2 * (1.0f / Cdim) - mu * mu;
    const float inv = rsqrtf(var + EPS);

    const float4* gg = reinterpret_cast<const float4*>(ln_e_g);
    const float4* bb = reinterpret_cast<const float4*>(ln_e_b);
    float4* orow = reinterpret_cast<float4*>(out + (size_t)gwarp * Cdim);
    #pragma unroll
    for (int c = 0; c < 8; c++) {
        const float4 g  = gg[lane + 32 * c];
        const float4 bt = bb[lane + 32 * c];
        float4 o;
        o.x = (v[c].x - mu) * inv * g.x + bt.x;
        o.y = (v[c].y - mu) * inv * g.y + bt.y;
        o.z = (v[c].z - mu) * inv * g.z + bt.z;
        o.w = (v[c].w - mu) * inv * g.w + bt.w;
        orow[lane + 32 * c] = o;
    }

    // Auxiliary outputs appended after the main tensor if the buffer has room
    const long long XSZ = (long long)NROWS * Cdim;
    if (out_size >= XSZ + (long long)NROWS) {
        if (lane == 0) out[XSZ + gwarp] = (t2 >= l + 2) ? 1.0f : 0.0f;
        if (lane == 1 && t2 == 0 && out_size >= XSZ + (long long)NROWS + Bdim)
            out[XSZ + (long long)NROWS + b] = (float)(l + 2);
    }
}

extern "C" void kernel_launch(void* const* d_in, const int* in_sizes, int n_in,
                              void* d_out, int out_size) {
    const float* x         = (const float*)d_in[0];
    const int*   lengths   = (const int*)  d_in[1];
    const float* bos_emb   = (const float*)d_in[2];
    const float* eos_emb   = (const float*)d_in[3];
    const float* ln_s_g    = (const float*)d_in[4];
    const float* ln_s_b    = (const float*)d_in[5];
    const float* pos_table = (const float*)d_in[6];
    const float* scale     = (const float*)d_in[7];
    const float* ln_e_g    = (const float*)d_in[8];
    const float* ln_e_b    = (const float*)d_in[9];
    float* out = (float*)d_out;

    const int grid = (NROWS + WARPS_PER_CTA - 1) / WARPS_PER_CTA;
    embed_kernel<<<grid, WARPS_PER_CTA * 32>>>(
        x, lengths, bos_emb, eos_emb, ln_s_g, ln_s_b,
        pos_table, scale, ln_e_g, ln_e_b, out, (long long)out_size);
}